// round 16
// baseline (speedup 1.0000x reference)
#include <cuda_runtime.h>
#include <cuda_fp16.h>
#include <math.h>
#include <cstdint>
#include <cstddef>

// ---------------- problem constants ----------------
#define S    2048
#define Hh   4096
#define NH   32
#define DN   128
#define DR   64
#define DV   128
#define QKD  192          // DN + DR
#define RQ   1536
#define RKV  512
#define CKVW 576          // RKV + DR
#define W1N  (RQ + CKVW)  // 2112

#define SM_SCALE 0.072168783648703220563f   // 192^-0.5

// ---- fp16 GEMM tiling: 128x256x64, slab-split smem (L=16 halfs), 3 stages ----
#define HBM 128
#define HBN 256
#define HBK 64
#define HSTG 3
#define A_ST_H (HBM * HBK)          // 8192 halfs per stage
#define B_ST_H (HBN * HBK)          // 16384 halfs per stage
#define STG_H  (A_ST_H + B_ST_H)    // 24576 halfs
#define GEMM_SMEM (HSTG * STG_H * 2)   // 147456 B

// ---------------- scratch (device globals; allocation-free) ----------------
__device__ float  g_qackv[S * W1N];            // [q_a | ckv] f32 (rmsnorm + k_rot source)
__device__ __half g_qan [S * RQ];
__device__ __half g_q   [S * NH * QKD];        // half now
__device__ __half g_ckvn[S * RKV];
__device__ __half g_kv  [S * NH * (DN+DV)];    // half now
__device__ __half g_Q   [(size_t)NH * S * QKD];
__device__ __half g_K   [(size_t)NH * S * QKD];
__device__ __half g_Vt  [(size_t)NH * DV * S]; // transposed: [h][d][s]
__device__ __half g_attn[S * Hh];
// fp16 copies of inputs
__device__ __half g_hid [S * Hh];
__device__ __half g_w1  [(size_t)W1N * Hh];
__device__ __half g_qbw [NH * QKD * RQ];
__device__ __half g_kvbw[NH * (DN+DV) * RKV];
__device__ __half g_ow  [(size_t)Hh * Hh];

// ---------------- helpers ----------------
__device__ __forceinline__ void cp_async16(void* smem, const void* gmem, bool pred) {
    unsigned int s = (unsigned int)__cvta_generic_to_shared(smem);
    int sz = pred ? 16 : 0;
    asm volatile("cp.async.cg.shared.global [%0], [%1], 16, %2;\n" :: "r"(s), "l"(gmem), "r"(sz));
}
__device__ __forceinline__ void cp_async_commit() { asm volatile("cp.async.commit_group;\n"); }
template<int N_> __device__ __forceinline__ void cp_async_wait() { asm volatile("cp.async.wait_group %0;\n" :: "n"(N_)); }

__device__ __forceinline__ uint32_t pack2h(float a, float b) {
    __half2 h = __floats2half2_rn(a, b);
    return *reinterpret_cast<uint32_t*>(&h);
}
// m16n8k16 fp16 MMA, f32 accumulate. A row-major, B col-major.
__device__ __forceinline__ void mma_f16(float* c, const uint32_t* a, uint32_t b0, uint32_t b1) {
    asm("mma.sync.aligned.m16n8k16.row.col.f32.f16.f16.f32 "
        "{%0,%1,%2,%3},{%4,%5,%6,%7},{%8,%9},{%0,%1,%2,%3};"
        : "+f"(c[0]), "+f"(c[1]), "+f"(c[2]), "+f"(c[3])
        : "r"(a[0]), "r"(a[1]), "r"(a[2]), "r"(a[3]), "r"(b0), "r"(b1));
}

// ---------------- f32 -> f16 conversion (vectorized) ----------------
__global__ void to_half_kernel(const float4* __restrict__ in, uint2* __restrict__ out, int n4) {
    int i = blockIdx.x * blockDim.x + threadIdx.x;
    if (i < n4) {
        float4 v = in[i];
        uint2 o;
        o.x = pack2h(v.x, v.y);
        o.y = pack2h(v.z, v.w);
        out[i] = o;
    }
}

// ============ fp16 NT GEMM: C[M,N] = A[M,K] * B[N,K]^T ============
// 8 warps 2(M)x4(N), warp tile 64x64. Per stage: 4 slabs of 16 k.
// k-permuted fragment slots: thread t holds k = {4t..4t+3}. HALF_OUT: C is __half.
template<bool HALF_OUT>
__global__ __launch_bounds__(256, 1)
void gemm_h(const __half* __restrict__ A, const __half* __restrict__ B,
            void* __restrict__ Cv, int M, int N, int K) {
    extern __shared__ __half smh[];
    const int tid  = threadIdx.x;
    const int warp = tid >> 5, lane = tid & 31;
    const int g    = lane >> 2, t = lane & 3;
    const int wm   = warp >> 2, wn = warp & 3;
    const int bm   = blockIdx.y * HBM, bn = blockIdx.x * HBN;

    float c[4][8][4];
#pragma unroll
    for (int i = 0; i < 4; i++)
#pragma unroll
        for (int j = 0; j < 8; j++) { c[i][j][0] = c[i][j][1] = c[i][j][2] = c[i][j][3] = 0.f; }

    const int T = K / HBK;

    auto load_stage = [&](int kt, int stg) {
        __half* base = smh + stg * STG_H;
        const int k0 = kt * HBK;
        // A: 128 rows x 4 slabs x 2 chunks = 1024 chunks (4/thread)
#pragma unroll
        for (int u = 0; u < 4; u++) {
            int f = tid + u * 256;
            int row = f >> 3, rem = f & 7;
            int slab = rem >> 1, c8 = (rem & 1) * 8;
            cp_async16(base + slab * 2048 + row * 16 + c8,
                       A + (size_t)(bm + row) * K + k0 + slab * 16 + c8, true);
        }
        // B: 256 rows x 4 slabs x 2 chunks = 2048 chunks (8/thread)
#pragma unroll
        for (int u = 0; u < 8; u++) {
            int f = tid + u * 256;
            int row = f >> 3, rem = f & 7;
            int slab = rem >> 1, c8 = (rem & 1) * 8;
            bool p = (bn + row) < N;
            cp_async16(base + A_ST_H + slab * 4096 + row * 16 + c8,
                       B + (size_t)(p ? (bn + row) : 0) * K + k0 + slab * 16 + c8, p);
        }
        cp_async_commit();
    };

#pragma unroll
    for (int s = 0; s < HSTG - 1; s++) {
        if (s < T) load_stage(s, s); else cp_async_commit();
    }

    for (int kt = 0; kt < T; kt++) {
        cp_async_wait<HSTG - 2>();
        __syncthreads();
        if (kt + HSTG - 1 < T) load_stage(kt + HSTG - 1, (kt + HSTG - 1) % HSTG);
        else cp_async_commit();

        const __half* base = smh + (kt % HSTG) * STG_H;
#pragma unroll
        for (int s = 0; s < 4; s++) {
            const __half* As = base + s * 2048;
            const __half* Bs = base + A_ST_H + s * 4096;
            uint32_t a[4][4];
#pragma unroll
            for (int i = 0; i < 4; i++) {
                const int rb = wm * 64 + i * 16;
                uint2 v0 = *(const uint2*)(As + (rb + g) * 16 + 4 * t);
                uint2 v1 = *(const uint2*)(As + (rb + g + 8) * 16 + 4 * t);
                a[i][0] = v0.x; a[i][1] = v1.x; a[i][2] = v0.y; a[i][3] = v1.y;
            }
            uint32_t bf[8][2];
#pragma unroll
            for (int j = 0; j < 8; j++) {
                const int nb = wn * 64 + j * 8;
                uint2 vb = *(const uint2*)(Bs + (nb + g) * 16 + 4 * t);
                bf[j][0] = vb.x; bf[j][1] = vb.y;
            }
#pragma unroll
            for (int i = 0; i < 4; i++)
#pragma unroll
                for (int j = 0; j < 8; j++)
                    mma_f16(c[i][j], a[i], bf[j][0], bf[j][1]);
        }
        __syncthreads();
    }

#pragma unroll
    for (int i = 0; i < 4; i++) {
        const int gm0 = bm + wm * 64 + i * 16 + g;
        const int gm1 = gm0 + 8;
#pragma unroll
        for (int j = 0; j < 8; j++) {
            const int gn = bn + wn * 64 + j * 8 + 2 * t;   // always even
            if (gn < N) {
                if (HALF_OUT) {
                    __half* C = (__half*)Cv;
                    *(uint32_t*)&C[(size_t)gm0 * N + gn] = pack2h(c[i][j][0], c[i][j][1]);
                    *(uint32_t*)&C[(size_t)gm1 * N + gn] = pack2h(c[i][j][2], c[i][j][3]);
                } else {
                    float* C = (float*)Cv;
                    float2 v0; v0.x = c[i][j][0]; v0.y = c[i][j][1];
                    float2 v1; v1.x = c[i][j][2]; v1.y = c[i][j][3];
                    *(float2*)&C[(size_t)gm0 * N + gn] = v0;
                    *(float2*)&C[(size_t)gm1 * N + gn] = v1;
                }
            }
        }
    }
}

// ================== fused flash attention (fp16 mma.sync) — unchanged R15 ==================
#define KSH 12288
#define VSH 8192
#define PS_LDH 80
#define PSH (16 * PS_LDH)
#define FLASH_SMEM ((2 * KSH + 2 * VSH + 8 * PSH) * 2)

__global__ __launch_bounds__(256, 1)
void flash_attn(const __half* __restrict__ Qb, const __half* __restrict__ Kb,
                const __half* __restrict__ Vtb, __half* __restrict__ Out) {
    extern __shared__ __half smh[];
    __half* KsB = smh;
    __half* VsB = smh + 2 * KSH;
    __half* PsB = smh + 2 * KSH + 2 * VSH;

    const int qt   = (int)(gridDim.x - 1 - blockIdx.x);  // heavy tiles first
    const int h    = blockIdx.y;
    const int bm   = qt * 128;
    const int tid  = threadIdx.x;
    const int warp = tid >> 5, lane = tid & 31;
    const int g    = lane >> 2, t = lane & 3;
    const int row0 = bm + warp * 16 + g;
    const int row1 = row0 + 8;

    const __half* Qh  = Qb  + (size_t)h * S * QKD;
    const __half* Kh  = Kb  + (size_t)h * S * QKD;
    const __half* Vth = Vtb + (size_t)h * DV * S;
    __half* Pw = PsB + warp * PSH;

    uint32_t qa[12][4];
    {
        const __half* q0 = Qh + (size_t)row0 * QKD;
        const __half* q1 = Qh + (size_t)row1 * QKD;
#pragma unroll
        for (int kg = 0; kg < 12; kg++) {
            uint2 w0 = *(const uint2*)(q0 + 16 * kg + 4 * t);
            uint2 w1 = *(const uint2*)(q1 + 16 * kg + 4 * t);
            qa[kg][0] = w0.x; qa[kg][1] = w1.x; qa[kg][2] = w0.y; qa[kg][3] = w1.y;
        }
    }

    float o[16][4];
#pragma unroll
    for (int i = 0; i < 16; i++) { o[i][0] = o[i][1] = o[i][2] = o[i][3] = 0.f; }
    float m0 = -1e30f, m1 = -1e30f, l0 = 0.f, l1 = 0.f;

    const int NT = 2 * qt + 2;

    auto load_kv = [&](int jtile, int buf) {
        __half* kdst = KsB + buf * KSH;
        const __half* ksrc = Kh + (size_t)(64 * jtile) * QKD;
#pragma unroll
        for (int i = 0; i < 6; i++) {
            int f = tid + i * 256;
            int row = f / 24, rem = f % 24;
            int slab = rem >> 1, c8 = (rem & 1) * 8;
            cp_async16(kdst + slab * 1024 + row * 16 + c8,
                       ksrc + (size_t)row * QKD + slab * 16 + c8, true);
        }
        __half* vdst = VsB + buf * VSH;
        const __half* vsrc = Vth;
#pragma unroll
        for (int i = 0; i < 4; i++) {
            int f = tid + i * 256;
            int row = f >> 3, rem = f & 7;
            int slab = rem >> 1, c8 = (rem & 1) * 8;
            cp_async16(vdst + slab * 2048 + row * 16 + c8,
                       vsrc + (size_t)row * S + 64 * jtile + slab * 16 + c8, true);
        }
        cp_async_commit();
    };

    load_kv(0, 0);
    cp_async_commit();

    for (int jt = 0; jt < NT; jt++) {
        const int buf = jt & 1;
        __syncthreads();
        if (jt + 1 < NT) { load_kv(jt + 1, buf ^ 1); cp_async_wait<1>(); }
        else             { cp_async_wait<0>(); }
        __syncthreads();

        const __half* Kst = KsB + buf * KSH;
        const __half* Vst = VsB + buf * VSH;

        float sc[8][4];
#pragma unroll
        for (int njp = 0; njp < 4; njp++) {
            float s0[4] = {0.f, 0.f, 0.f, 0.f};
            float s1[4] = {0.f, 0.f, 0.f, 0.f};
            const int kr0 = ((2 * njp) * 8 + g) * 16 + 4 * t;
            const int kr1 = ((2 * njp + 1) * 8 + g) * 16 + 4 * t;
#pragma unroll
            for (int kg = 0; kg < 12; kg++) {
                uint2 vb0 = *(const uint2*)(Kst + kg * 1024 + kr0);
                mma_f16(s0, qa[kg], vb0.x, vb0.y);
                uint2 vb1 = *(const uint2*)(Kst + kg * 1024 + kr1);
                mma_f16(s1, qa[kg], vb1.x, vb1.y);
            }
#pragma unroll
            for (int e = 0; e < 4; e++) { sc[2 * njp][e] = s0[e]; sc[2 * njp + 1][e] = s1[e]; }
        }

#pragma unroll
        for (int nj = 0; nj < 8; nj++) {
            int colb = 64 * jt + 8 * nj + 2 * t;
            if (colb     > row0) sc[nj][0] = -1e30f;
            if (colb + 1 > row0) sc[nj][1] = -1e30f;
            if (colb     > row1) sc[nj][2] = -1e30f;
            if (colb + 1 > row1) sc[nj][3] = -1e30f;
        }

        float tm0 = -1e30f, tm1 = -1e30f;
#pragma unroll
        for (int nj = 0; nj < 8; nj++) {
            tm0 = fmaxf(tm0, fmaxf(sc[nj][0], sc[nj][1]));
            tm1 = fmaxf(tm1, fmaxf(sc[nj][2], sc[nj][3]));
        }
        tm0 = fmaxf(tm0, __shfl_xor_sync(0xffffffffu, tm0, 1));
        tm0 = fmaxf(tm0, __shfl_xor_sync(0xffffffffu, tm0, 2));
        tm1 = fmaxf(tm1, __shfl_xor_sync(0xffffffffu, tm1, 1));
        tm1 = fmaxf(tm1, __shfl_xor_sync(0xffffffffu, tm1, 2));
        const float nm0 = fmaxf(m0, tm0), nm1 = fmaxf(m1, tm1);
        const float al0 = expf((m0 - nm0) * SM_SCALE);
        const float al1 = expf((m1 - nm1) * SM_SCALE);

        float rs0 = 0.f, rs1 = 0.f;
#pragma unroll
        for (int nj = 0; nj < 8; nj++) {
            float p0 = expf((sc[nj][0] - nm0) * SM_SCALE);
            float p1 = expf((sc[nj][1] - nm0) * SM_SCALE);
            float p2 = expf((sc[nj][2] - nm1) * SM_SCALE);
            float p3 = expf((sc[nj][3] - nm1) * SM_SCALE);
            rs0 += p0 + p1;
            rs1 += p2 + p3;
            *(uint32_t*)(Pw + g * PS_LDH + 8 * nj + 2 * t)       = pack2h(p0, p1);
            *(uint32_t*)(Pw + (g + 8) * PS_LDH + 8 * nj + 2 * t) = pack2h(p2, p3);
        }
        l0 = l0 * al0 + rs0;
        l1 = l1 * al1 + rs1;
        m0 = nm0; m1 = nm1;
#pragma unroll
        for (int dj = 0; dj < 16; dj++) {
            o[dj][0] *= al0; o[dj][1] *= al0;
            o[dj][2] *= al1; o[dj][3] *= al1;
        }
        __syncwarp();

#pragma unroll
        for (int kg = 0; kg < 4; kg++) {
            uint32_t pa[4];
            uint2 pw0 = *(const uint2*)(Pw + g * PS_LDH + 16 * kg + 4 * t);
            uint2 pw1 = *(const uint2*)(Pw + (g + 8) * PS_LDH + 16 * kg + 4 * t);
            pa[0] = pw0.x; pa[1] = pw1.x; pa[2] = pw0.y; pa[3] = pw1.y;
            const __half* vs = Vst + kg * 2048;
#pragma unroll
            for (int dj = 0; dj < 16; dj += 2) {
                uint2 vb0 = *(const uint2*)(vs + (8 * dj + g) * 16 + 4 * t);
                mma_f16(o[dj], pa, vb0.x, vb0.y);
                uint2 vb1 = *(const uint2*)(vs + (8 * (dj + 1) + g) * 16 + 4 * t);
                mma_f16(o[dj + 1], pa, vb1.x, vb1.y);
            }
        }
        __syncwarp();
    }

    l0 += __shfl_xor_sync(0xffffffffu, l0, 1);
    l0 += __shfl_xor_sync(0xffffffffu, l0, 2);
    l1 += __shfl_xor_sync(0xffffffffu, l1, 1);
    l1 += __shfl_xor_sync(0xffffffffu, l1, 2);

    const float inv0 = 1.f / l0, inv1 = 1.f / l1;
    __half* or0 = Out + (size_t)row0 * Hh + h * DV;
    __half* or1 = Out + (size_t)row1 * Hh + h * DV;
#pragma unroll
    for (int dj = 0; dj < 16; dj++) {
        *(uint32_t*)(or0 + 8 * dj + 2 * t) = pack2h(o[dj][0] * inv0, o[dj][1] * inv0);
        *(uint32_t*)(or1 + 8 * dj + 2 * t) = pack2h(o[dj][2] * inv1, o[dj][3] * inv1);
    }
}

// ---------------- rmsnorm over first K cols; half output ----------------
__global__ void rmsnorm_kernel(const float* __restrict__ X, const float* __restrict__ w,
                               __half* __restrict__ Y, int K, int ldx, int ldy) {
    const int row = blockIdx.x;
    const float* x = X + (size_t)row * ldx;
    __half* y = Y + (size_t)row * ldy;
    float ss = 0.f;
    for (int j = threadIdx.x; j < K; j += blockDim.x) { float v = x[j]; ss += v * v; }
    __shared__ float red[256];
    red[threadIdx.x] = ss;
    __syncthreads();
    for (int s = 128; s > 0; s >>= 1) {
        if (threadIdx.x < s) red[threadIdx.x] += red[threadIdx.x + s];
        __syncthreads();
    }
    float inv = rsqrtf(red[0] / (float)K + 1e-6f);
    for (int j = threadIdx.x; j < K; j += blockDim.x)
        y[j] = __float2half_rn(x[j] * inv * w[j]);
}

// ---------------- build Q (RoPE), half in/out ----------------
__global__ void build_q2(const __half* __restrict__ q, const float* __restrict__ freqs,
                         __half* __restrict__ Qb) {
    const int s = blockIdx.x;
    __shared__ float cs[DR];
    if (threadIdx.x < DR / 2) {
        float f = freqs[s * (DR / 2) + threadIdx.x];
        cs[threadIdx.x]      = cosf(f);
        cs[32 + threadIdx.x] = sinf(f);
    }
    __syncthreads();
    const __half* qs = q + (size_t)s * (NH * QKD);
    for (int idx = threadIdx.x; idx < NH * QKD; idx += 256) {
        int h = idx / QKD, d = idx - h * QKD;
        if (d < DN) {
            Qb[((size_t)h * S + s) * QKD + d] = qs[h * QKD + d];
        } else {
            int u = d - DN, t = u >> 1;
            float c = cs[t], sn = cs[32 + t];
            float xr = __half2float(qs[h * QKD + DN + 2 * t]);
            float xi = __half2float(qs[h * QKD + DN + 2 * t + 1]);
            float val = (u & 1) ? (xr * sn + xi * c) : (xr * c - xi * sn);
            Qb[((size_t)h * S + s) * QKD + d] = __float2half_rn(val);
        }
    }
}

// ---------------- build K (RoPE from f32 ckv, shared rot), half out ----------------
__global__ void build_k2(const __half* __restrict__ kv, const float* __restrict__ qackv,
                         const float* __restrict__ freqs, __half* __restrict__ Kb) {
    const int s = blockIdx.x;
    __shared__ __half rot[DR];
    if (threadIdx.x < DR / 2) {
        float f = freqs[s * (DR / 2) + threadIdx.x];
        float c = cosf(f), sn = sinf(f);
        const float* kr = qackv + (size_t)s * W1N + (RQ + RKV);
        float xr = kr[2 * threadIdx.x], xi = kr[2 * threadIdx.x + 1];
        rot[2 * threadIdx.x]     = __float2half_rn(xr * c - xi * sn);
        rot[2 * threadIdx.x + 1] = __float2half_rn(xr * sn + xi * c);
    }
    __syncthreads();
    const __half* kvs = kv + (size_t)s * (NH * (DN + DV));
    for (int idx = threadIdx.x; idx < NH * QKD; idx += 256) {
        int h = idx / QKD, d = idx - h * QKD;
        if (d < DN) {
            Kb[((size_t)h * S + s) * QKD + d] = kvs[h * (DN + DV) + d];
        } else {
            Kb[((size_t)h * S + s) * QKD + d] = rot[d - DN];
        }
    }
}

// ---------------- V transpose: kv half [s][h][DN+d] -> Vt half [h][d][s] ----------------
__global__ void vtrans(const __half* __restrict__ kv, __half* __restrict__ Vt) {
    const int h = blockIdx.x, d0 = blockIdx.y * 32, s0 = blockIdx.z * 64;
    __shared__ __half tile[32][65];
    const int dl = threadIdx.x & 31, sl = threadIdx.x >> 5;
    for (int ss = sl; ss < 64; ss += 8)
        tile[dl][ss] = kv[(size_t)(s0 + ss) * (NH * (DN + DV)) + h * (DN + DV) + DN + d0 + dl];
    __syncthreads();
    const int sl2 = threadIdx.x & 63, dl2 = threadIdx.x >> 6;
    for (int dd = dl2; dd < 32; dd += 4)
        Vt[((size_t)h * DV + d0 + dd) * S + s0 + sl2] = tile[dd][sl2];
}

// ---------------- host ----------------
static void* sym_addr(const void* symbol) {
    void* p = nullptr;
    cudaGetSymbolAddress(&p, symbol);
    return p;
}

static void launch_half(const float* src, __half* dst, size_t n) {
    int n4 = (int)(n / 4);
    to_half_kernel<<<(n4 + 255) / 256, 256>>>((const float4*)src, (uint2*)dst, n4);
}

static void launch_gemm_f(const __half* A, const __half* B, float* C, int M, int N, int K) {
    dim3 grid((N + HBN - 1) / HBN, M / HBM);
    gemm_h<false><<<grid, 256, GEMM_SMEM>>>(A, B, C, M, N, K);
}
static void launch_gemm_hh(const __half* A, const __half* B, __half* C, int M, int N, int K) {
    dim3 grid((N + HBN - 1) / HBN, M / HBM);
    gemm_h<true><<<grid, 256, GEMM_SMEM>>>(A, B, C, M, N, K);
}

extern "C" void kernel_launch(void* const* d_in, const int* in_sizes, int n_in,
                              void* d_out, int out_size) {
    const float* hidden    = (const float*)d_in[0];
    const float* freqs     = (const float*)d_in[1];
    const float* q_a_w     = (const float*)d_in[2];
    const float* q_a_ln_w  = (const float*)d_in[3];
    const float* q_b_w     = (const float*)d_in[4];
    const float* kv_a_w    = (const float*)d_in[5];
    const float* kv_a_ln_w = (const float*)d_in[6];
    const float* kv_b_w    = (const float*)d_in[7];
    const float* o_w       = (const float*)d_in[8];
    float* out = (float*)d_out;

    float*  qackv = (float*) sym_addr(g_qackv);
    __half* qan   = (__half*)sym_addr(g_qan);
    __half* q     = (__half*)sym_addr(g_q);
    __half* ckvn  = (__half*)sym_addr(g_ckvn);
    __half* kv    = (__half*)sym_addr(g_kv);
    __half* Qb    = (__half*)sym_addr(g_Q);
    __half* Kb    = (__half*)sym_addr(g_K);
    __half* Vt    = (__half*)sym_addr(g_Vt);
    __half* attn  = (__half*)sym_addr(g_attn);
    __half* hid   = (__half*)sym_addr(g_hid);
    __half* w1    = (__half*)sym_addr(g_w1);
    __half* qbw   = (__half*)sym_addr(g_qbw);
    __half* kvbw  = (__half*)sym_addr(g_kvbw);
    __half* ow    = (__half*)sym_addr(g_ow);

    cudaFuncSetAttribute(flash_attn, cudaFuncAttributeMaxDynamicSharedMemorySize, FLASH_SMEM);
    cudaFuncSetAttribute(gemm_h<false>, cudaFuncAttributeMaxDynamicSharedMemorySize, GEMM_SMEM);
    cudaFuncSetAttribute(gemm_h<true>,  cudaFuncAttributeMaxDynamicSharedMemorySize, GEMM_SMEM);

    // 0) convert inputs to fp16 once per call
    launch_half(hidden, hid,  (size_t)S * Hh);
    launch_half(q_a_w,  w1,                    (size_t)RQ * Hh);
    launch_half(kv_a_w, w1 + (size_t)RQ * Hh,  (size_t)CKVW * Hh);
    launch_half(q_b_w,  qbw,  (size_t)NH * QKD * RQ);
    launch_half(kv_b_w, kvbw, (size_t)NH * (DN + DV) * RKV);
    launch_half(o_w,    ow,   (size_t)Hh * Hh);

    // 1) [q_a | ckv] = hid @ w1^T   [2048, 2112] (f32 out for rmsnorm + k_rot)
    launch_gemm_f(hid, w1, qackv, S, W1N, Hh);
    // 2) rmsnorm(q_a) -> half
    rmsnorm_kernel<<<S, 256>>>(qackv, q_a_ln_w, qan, RQ, W1N, RQ);
    // 3) q = qan @ qbw^T            [2048,6144] (half out)
    launch_gemm_hh(qan, qbw, q, S, NH * QKD, RQ);
    // 5) rmsnorm(ckv[:, :512]) -> half
    rmsnorm_kernel<<<S, 256>>>(qackv + RQ, kv_a_ln_w, ckvn, RKV, W1N, RKV);
    // 6) kv = ckvn @ kvbw^T         [2048,8192] (half out)
    launch_gemm_hh(ckvn, kvbw, kv, S, NH * (DN + DV), RKV);
    // 7) assemble Q with RoPE (half)
    build_q2<<<S, 256>>>(q, freqs, Qb);
    // 8) assemble K (half); V transposed [h][d][s]
    build_k2<<<S, 256>>>(kv, qackv, freqs, Kb);
    vtrans<<<dim3(NH, DV / 32, S / 64), 256>>>(kv, Vt);
    // 9-11) fused flash attention -> attn (half)
    flash_attn<<<dim3(S / 128, NH), 256, FLASH_SMEM>>>(Qb, Kb, Vt, attn);
    // 12) out = attn @ ow^T         [2048,4096] (f32 out)
    launch_gemm_f(attn, ow, out, S, Hh, Hh);
}

// round 17
// speedup vs baseline: 1.0130x; 1.0130x over previous
#include <cuda_runtime.h>
#include <cuda_fp16.h>
#include <math.h>
#include <cstdint>
#include <cstddef>

// ---------------- problem constants ----------------
#define S    2048
#define Hh   4096
#define NH   32
#define DN   128
#define DR   64
#define DV   128
#define QKD  192          // DN + DR
#define RQ   1536
#define RKV  512
#define CKVW 576          // RKV + DR
#define W1N  (RQ + CKVW)  // 2112

#define SM_SCALE 0.072168783648703220563f   // 192^-0.5

// ---- fp16 GEMM tiling: 128x256x32, slab-split smem (L=16 halfs), 4 stages (R15 proven) ----
#define HBM 128
#define HBN 256
#define HBK 32
#define HSTG 4
#define A_ST_H (HBM * HBK)          // 4096 halfs per stage
#define B_ST_H (HBN * HBK)          // 8192 halfs per stage
#define STG_H  (A_ST_H + B_ST_H)    // 12288 halfs
#define GEMM_SMEM (HSTG * STG_H * 2)   // 98304 B

// ---------------- scratch (device globals; allocation-free) ----------------
__device__ float  g_qackv[S * W1N];            // [q_a | ckv] f32 (rmsnorm + k_rot source)
__device__ __half g_qan [S * RQ];
__device__ __half g_q   [S * NH * QKD];        // half
__device__ __half g_ckvn[S * RKV];
__device__ __half g_kv  [S * NH * (DN+DV)];    // half
__device__ __half g_Q   [(size_t)NH * S * QKD];
__device__ __half g_K   [(size_t)NH * S * QKD];
__device__ __half g_Vt  [(size_t)NH * DV * S]; // transposed: [h][d][s]
__device__ __half g_attn[S * Hh];
// fp16 copies of inputs
__device__ __half g_hid [S * Hh];
__device__ __half g_w1  [(size_t)W1N * Hh];
__device__ __half g_qbw [NH * QKD * RQ];
__device__ __half g_kvbw[NH * (DN+DV) * RKV];
__device__ __half g_ow  [(size_t)Hh * Hh];

// ---------------- helpers ----------------
__device__ __forceinline__ void cp_async16(void* smem, const void* gmem, bool pred) {
    unsigned int s = (unsigned int)__cvta_generic_to_shared(smem);
    int sz = pred ? 16 : 0;
    asm volatile("cp.async.cg.shared.global [%0], [%1], 16, %2;\n" :: "r"(s), "l"(gmem), "r"(sz));
}
__device__ __forceinline__ void cp_async_commit() { asm volatile("cp.async.commit_group;\n"); }
template<int N_> __device__ __forceinline__ void cp_async_wait() { asm volatile("cp.async.wait_group %0;\n" :: "n"(N_)); }

__device__ __forceinline__ uint32_t pack2h(float a, float b) {
    __half2 h = __floats2half2_rn(a, b);
    return *reinterpret_cast<uint32_t*>(&h);
}
// m16n8k16 fp16 MMA, f32 accumulate. A row-major, B col-major.
__device__ __forceinline__ void mma_f16(float* c, const uint32_t* a, uint32_t b0, uint32_t b1) {
    asm("mma.sync.aligned.m16n8k16.row.col.f32.f16.f16.f32 "
        "{%0,%1,%2,%3},{%4,%5,%6,%7},{%8,%9},{%0,%1,%2,%3};"
        : "+f"(c[0]), "+f"(c[1]), "+f"(c[2]), "+f"(c[3])
        : "r"(a[0]), "r"(a[1]), "r"(a[2]), "r"(a[3]), "r"(b0), "r"(b1));
}

// ---------------- f32 -> f16 conversion (vectorized) ----------------
__global__ void to_half_kernel(const float4* __restrict__ in, uint2* __restrict__ out, int n4) {
    int i = blockIdx.x * blockDim.x + threadIdx.x;
    if (i < n4) {
        float4 v = in[i];
        uint2 o;
        o.x = pack2h(v.x, v.y);
        o.y = pack2h(v.z, v.w);
        out[i] = o;
    }
}

// ============ fp16 NT GEMM: C[M,N] = A[M,K] * B[N,K]^T ============
// 8 warps 2(M)x4(N), warp tile 64x64. Per stage: 2 slabs of 16 k.
// k-permuted fragment slots: thread t holds k = {4t..4t+3}. HALF_OUT: C is __half.
template<bool HALF_OUT>
__global__ __launch_bounds__(256, 1)
void gemm_h(const __half* __restrict__ A, const __half* __restrict__ B,
            void* __restrict__ Cv, int M, int N, int K) {
    extern __shared__ __half smh[];
    const int tid  = threadIdx.x;
    const int warp = tid >> 5, lane = tid & 31;
    const int g    = lane >> 2, t = lane & 3;
    const int wm   = warp >> 2, wn = warp & 3;
    const int bm   = blockIdx.y * HBM, bn = blockIdx.x * HBN;

    float c[4][8][4];
#pragma unroll
    for (int i = 0; i < 4; i++)
#pragma unroll
        for (int j = 0; j < 8; j++) { c[i][j][0] = c[i][j][1] = c[i][j][2] = c[i][j][3] = 0.f; }

    const int T = K / HBK;

    auto load_stage = [&](int kt, int stg) {
        __half* base = smh + stg * STG_H;
        const int k0 = kt * HBK;
        // A: 128 rows x 2 slabs x 2 chunks = 512 chunks (2/thread)
#pragma unroll
        for (int u = 0; u < 2; u++) {
            int f = tid + u * 256;
            int row = f >> 2, rem = f & 3;
            int slab = rem >> 1, c8 = (rem & 1) * 8;
            cp_async16(base + slab * 2048 + row * 16 + c8,
                       A + (size_t)(bm + row) * K + k0 + slab * 16 + c8, true);
        }
        // B: 256 rows x 2 slabs x 2 chunks = 1024 chunks (4/thread)
#pragma unroll
        for (int u = 0; u < 4; u++) {
            int f = tid + u * 256;
            int row = f >> 2, rem = f & 3;
            int slab = rem >> 1, c8 = (rem & 1) * 8;
            bool p = (bn + row) < N;
            cp_async16(base + A_ST_H + slab * 4096 + row * 16 + c8,
                       B + (size_t)(p ? (bn + row) : 0) * K + k0 + slab * 16 + c8, p);
        }
        cp_async_commit();
    };

#pragma unroll
    for (int s = 0; s < HSTG - 1; s++) {
        if (s < T) load_stage(s, s); else cp_async_commit();
    }

    for (int kt = 0; kt < T; kt++) {
        cp_async_wait<HSTG - 2>();
        __syncthreads();
        if (kt + HSTG - 1 < T) load_stage(kt + HSTG - 1, (kt + HSTG - 1) % HSTG);
        else cp_async_commit();

        const __half* base = smh + (kt % HSTG) * STG_H;
#pragma unroll
        for (int s = 0; s < 2; s++) {
            const __half* As = base + s * 2048;
            const __half* Bs = base + A_ST_H + s * 4096;
            uint32_t a[4][4];
#pragma unroll
            for (int i = 0; i < 4; i++) {
                const int rb = wm * 64 + i * 16;
                uint2 v0 = *(const uint2*)(As + (rb + g) * 16 + 4 * t);
                uint2 v1 = *(const uint2*)(As + (rb + g + 8) * 16 + 4 * t);
                a[i][0] = v0.x; a[i][1] = v1.x; a[i][2] = v0.y; a[i][3] = v1.y;
            }
            uint32_t bf[8][2];
#pragma unroll
            for (int j = 0; j < 8; j++) {
                const int nb = wn * 64 + j * 8;
                uint2 vb = *(const uint2*)(Bs + (nb + g) * 16 + 4 * t);
                bf[j][0] = vb.x; bf[j][1] = vb.y;
            }
#pragma unroll
            for (int i = 0; i < 4; i++)
#pragma unroll
                for (int j = 0; j < 8; j++)
                    mma_f16(c[i][j], a[i], bf[j][0], bf[j][1]);
        }
        __syncthreads();
    }

#pragma unroll
    for (int i = 0; i < 4; i++) {
        const int gm0 = bm + wm * 64 + i * 16 + g;
        const int gm1 = gm0 + 8;
#pragma unroll
        for (int j = 0; j < 8; j++) {
            const int gn = bn + wn * 64 + j * 8 + 2 * t;   // always even
            if (gn < N) {
                if (HALF_OUT) {
                    __half* C = (__half*)Cv;
                    *(uint32_t*)&C[(size_t)gm0 * N + gn] = pack2h(c[i][j][0], c[i][j][1]);
                    *(uint32_t*)&C[(size_t)gm1 * N + gn] = pack2h(c[i][j][2], c[i][j][3]);
                } else {
                    float* C = (float*)Cv;
                    float2 v0; v0.x = c[i][j][0]; v0.y = c[i][j][1];
                    float2 v1; v1.x = c[i][j][2]; v1.y = c[i][j][3];
                    *(float2*)&C[(size_t)gm0 * N + gn] = v0;
                    *(float2*)&C[(size_t)gm1 * N + gn] = v1;
                }
            }
        }
    }
}

// ================== fused flash attention (fp16 mma.sync) — unchanged R15 ==================
#define KSH 12288
#define VSH 8192
#define PS_LDH 80
#define PSH (16 * PS_LDH)
#define FLASH_SMEM ((2 * KSH + 2 * VSH + 8 * PSH) * 2)

__global__ __launch_bounds__(256, 1)
void flash_attn(const __half* __restrict__ Qb, const __half* __restrict__ Kb,
                const __half* __restrict__ Vtb, __half* __restrict__ Out) {
    extern __shared__ __half smh[];
    __half* KsB = smh;
    __half* VsB = smh + 2 * KSH;
    __half* PsB = smh + 2 * KSH + 2 * VSH;

    const int qt   = (int)(gridDim.x - 1 - blockIdx.x);  // heavy tiles first
    const int h    = blockIdx.y;
    const int bm   = qt * 128;
    const int tid  = threadIdx.x;
    const int warp = tid >> 5, lane = tid & 31;
    const int g    = lane >> 2, t = lane & 3;
    const int row0 = bm + warp * 16 + g;
    const int row1 = row0 + 8;

    const __half* Qh  = Qb  + (size_t)h * S * QKD;
    const __half* Kh  = Kb  + (size_t)h * S * QKD;
    const __half* Vth = Vtb + (size_t)h * DV * S;
    __half* Pw = PsB + warp * PSH;

    uint32_t qa[12][4];
    {
        const __half* q0 = Qh + (size_t)row0 * QKD;
        const __half* q1 = Qh + (size_t)row1 * QKD;
#pragma unroll
        for (int kg = 0; kg < 12; kg++) {
            uint2 w0 = *(const uint2*)(q0 + 16 * kg + 4 * t);
            uint2 w1 = *(const uint2*)(q1 + 16 * kg + 4 * t);
            qa[kg][0] = w0.x; qa[kg][1] = w1.x; qa[kg][2] = w0.y; qa[kg][3] = w1.y;
        }
    }

    float o[16][4];
#pragma unroll
    for (int i = 0; i < 16; i++) { o[i][0] = o[i][1] = o[i][2] = o[i][3] = 0.f; }
    float m0 = -1e30f, m1 = -1e30f, l0 = 0.f, l1 = 0.f;

    const int NT = 2 * qt + 2;

    auto load_kv = [&](int jtile, int buf) {
        __half* kdst = KsB + buf * KSH;
        const __half* ksrc = Kh + (size_t)(64 * jtile) * QKD;
#pragma unroll
        for (int i = 0; i < 6; i++) {
            int f = tid + i * 256;
            int row = f / 24, rem = f % 24;
            int slab = rem >> 1, c8 = (rem & 1) * 8;
            cp_async16(kdst + slab * 1024 + row * 16 + c8,
                       ksrc + (size_t)row * QKD + slab * 16 + c8, true);
        }
        __half* vdst = VsB + buf * VSH;
        const __half* vsrc = Vth;
#pragma unroll
        for (int i = 0; i < 4; i++) {
            int f = tid + i * 256;
            int row = f >> 3, rem = f & 7;
            int slab = rem >> 1, c8 = (rem & 1) * 8;
            cp_async16(vdst + slab * 2048 + row * 16 + c8,
                       vsrc + (size_t)row * S + 64 * jtile + slab * 16 + c8, true);
        }
        cp_async_commit();
    };

    load_kv(0, 0);
    cp_async_commit();

    for (int jt = 0; jt < NT; jt++) {
        const int buf = jt & 1;
        __syncthreads();
        if (jt + 1 < NT) { load_kv(jt + 1, buf ^ 1); cp_async_wait<1>(); }
        else             { cp_async_wait<0>(); }
        __syncthreads();

        const __half* Kst = KsB + buf * KSH;
        const __half* Vst = VsB + buf * VSH;

        float sc[8][4];
#pragma unroll
        for (int njp = 0; njp < 4; njp++) {
            float s0[4] = {0.f, 0.f, 0.f, 0.f};
            float s1[4] = {0.f, 0.f, 0.f, 0.f};
            const int kr0 = ((2 * njp) * 8 + g) * 16 + 4 * t;
            const int kr1 = ((2 * njp + 1) * 8 + g) * 16 + 4 * t;
#pragma unroll
            for (int kg = 0; kg < 12; kg++) {
                uint2 vb0 = *(const uint2*)(Kst + kg * 1024 + kr0);
                mma_f16(s0, qa[kg], vb0.x, vb0.y);
                uint2 vb1 = *(const uint2*)(Kst + kg * 1024 + kr1);
                mma_f16(s1, qa[kg], vb1.x, vb1.y);
            }
#pragma unroll
            for (int e = 0; e < 4; e++) { sc[2 * njp][e] = s0[e]; sc[2 * njp + 1][e] = s1[e]; }
        }

#pragma unroll
        for (int nj = 0; nj < 8; nj++) {
            int colb = 64 * jt + 8 * nj + 2 * t;
            if (colb     > row0) sc[nj][0] = -1e30f;
            if (colb + 1 > row0) sc[nj][1] = -1e30f;
            if (colb     > row1) sc[nj][2] = -1e30f;
            if (colb + 1 > row1) sc[nj][3] = -1e30f;
        }

        float tm0 = -1e30f, tm1 = -1e30f;
#pragma unroll
        for (int nj = 0; nj < 8; nj++) {
            tm0 = fmaxf(tm0, fmaxf(sc[nj][0], sc[nj][1]));
            tm1 = fmaxf(tm1, fmaxf(sc[nj][2], sc[nj][3]));
        }
        tm0 = fmaxf(tm0, __shfl_xor_sync(0xffffffffu, tm0, 1));
        tm0 = fmaxf(tm0, __shfl_xor_sync(0xffffffffu, tm0, 2));
        tm1 = fmaxf(tm1, __shfl_xor_sync(0xffffffffu, tm1, 1));
        tm1 = fmaxf(tm1, __shfl_xor_sync(0xffffffffu, tm1, 2));
        const float nm0 = fmaxf(m0, tm0), nm1 = fmaxf(m1, tm1);
        const float al0 = expf((m0 - nm0) * SM_SCALE);
        const float al1 = expf((m1 - nm1) * SM_SCALE);

        float rs0 = 0.f, rs1 = 0.f;
#pragma unroll
        for (int nj = 0; nj < 8; nj++) {
            float p0 = expf((sc[nj][0] - nm0) * SM_SCALE);
            float p1 = expf((sc[nj][1] - nm0) * SM_SCALE);
            float p2 = expf((sc[nj][2] - nm1) * SM_SCALE);
            float p3 = expf((sc[nj][3] - nm1) * SM_SCALE);
            rs0 += p0 + p1;
            rs1 += p2 + p3;
            *(uint32_t*)(Pw + g * PS_LDH + 8 * nj + 2 * t)       = pack2h(p0, p1);
            *(uint32_t*)(Pw + (g + 8) * PS_LDH + 8 * nj + 2 * t) = pack2h(p2, p3);
        }
        l0 = l0 * al0 + rs0;
        l1 = l1 * al1 + rs1;
        m0 = nm0; m1 = nm1;
#pragma unroll
        for (int dj = 0; dj < 16; dj++) {
            o[dj][0] *= al0; o[dj][1] *= al0;
            o[dj][2] *= al1; o[dj][3] *= al1;
        }
        __syncwarp();

#pragma unroll
        for (int kg = 0; kg < 4; kg++) {
            uint32_t pa[4];
            uint2 pw0 = *(const uint2*)(Pw + g * PS_LDH + 16 * kg + 4 * t);
            uint2 pw1 = *(const uint2*)(Pw + (g + 8) * PS_LDH + 16 * kg + 4 * t);
            pa[0] = pw0.x; pa[1] = pw1.x; pa[2] = pw0.y; pa[3] = pw1.y;
            const __half* vs = Vst + kg * 2048;
#pragma unroll
            for (int dj = 0; dj < 16; dj += 2) {
                uint2 vb0 = *(const uint2*)(vs + (8 * dj + g) * 16 + 4 * t);
                mma_f16(o[dj], pa, vb0.x, vb0.y);
                uint2 vb1 = *(const uint2*)(vs + (8 * (dj + 1) + g) * 16 + 4 * t);
                mma_f16(o[dj + 1], pa, vb1.x, vb1.y);
            }
        }
        __syncwarp();
    }

    l0 += __shfl_xor_sync(0xffffffffu, l0, 1);
    l0 += __shfl_xor_sync(0xffffffffu, l0, 2);
    l1 += __shfl_xor_sync(0xffffffffu, l1, 1);
    l1 += __shfl_xor_sync(0xffffffffu, l1, 2);

    const float inv0 = 1.f / l0, inv1 = 1.f / l1;
    __half* or0 = Out + (size_t)row0 * Hh + h * DV;
    __half* or1 = Out + (size_t)row1 * Hh + h * DV;
#pragma unroll
    for (int dj = 0; dj < 16; dj++) {
        *(uint32_t*)(or0 + 8 * dj + 2 * t) = pack2h(o[dj][0] * inv0, o[dj][1] * inv0);
        *(uint32_t*)(or1 + 8 * dj + 2 * t) = pack2h(o[dj][2] * inv1, o[dj][3] * inv1);
    }
}

// ---------------- rmsnorm over first K cols; half output ----------------
__global__ void rmsnorm_kernel(const float* __restrict__ X, const float* __restrict__ w,
                               __half* __restrict__ Y, int K, int ldx, int ldy) {
    const int row = blockIdx.x;
    const float* x = X + (size_t)row * ldx;
    __half* y = Y + (size_t)row * ldy;
    float ss = 0.f;
    for (int j = threadIdx.x; j < K; j += blockDim.x) { float v = x[j]; ss += v * v; }
    __shared__ float red[256];
    red[threadIdx.x] = ss;
    __syncthreads();
    for (int s = 128; s > 0; s >>= 1) {
        if (threadIdx.x < s) red[threadIdx.x] += red[threadIdx.x + s];
        __syncthreads();
    }
    float inv = rsqrtf(red[0] / (float)K + 1e-6f);
    for (int j = threadIdx.x; j < K; j += blockDim.x)
        y[j] = __float2half_rn(x[j] * inv * w[j]);
}

// ---------------- build Q (RoPE), half in/out ----------------
__global__ void build_q2(const __half* __restrict__ q, const float* __restrict__ freqs,
                         __half* __restrict__ Qb) {
    const int s = blockIdx.x;
    __shared__ float cs[DR];
    if (threadIdx.x < DR / 2) {
        float f = freqs[s * (DR / 2) + threadIdx.x];
        cs[threadIdx.x]      = cosf(f);
        cs[32 + threadIdx.x] = sinf(f);
    }
    __syncthreads();
    const __half* qs = q + (size_t)s * (NH * QKD);
    for (int idx = threadIdx.x; idx < NH * QKD; idx += 256) {
        int h = idx / QKD, d = idx - h * QKD;
        if (d < DN) {
            Qb[((size_t)h * S + s) * QKD + d] = qs[h * QKD + d];
        } else {
            int u = d - DN, t = u >> 1;
            float c = cs[t], sn = cs[32 + t];
            float xr = __half2float(qs[h * QKD + DN + 2 * t]);
            float xi = __half2float(qs[h * QKD + DN + 2 * t + 1]);
            float val = (u & 1) ? (xr * sn + xi * c) : (xr * c - xi * sn);
            Qb[((size_t)h * S + s) * QKD + d] = __float2half_rn(val);
        }
    }
}

// ---------------- build K (RoPE from f32 ckv, shared rot), half out ----------------
__global__ void build_k2(const __half* __restrict__ kv, const float* __restrict__ qackv,
                         const float* __restrict__ freqs, __half* __restrict__ Kb) {
    const int s = blockIdx.x;
    __shared__ __half rot[DR];
    if (threadIdx.x < DR / 2) {
        float f = freqs[s * (DR / 2) + threadIdx.x];
        float c = cosf(f), sn = sinf(f);
        const float* kr = qackv + (size_t)s * W1N + (RQ + RKV);
        float xr = kr[2 * threadIdx.x], xi = kr[2 * threadIdx.x + 1];
        rot[2 * threadIdx.x]     = __float2half_rn(xr * c - xi * sn);
        rot[2 * threadIdx.x + 1] = __float2half_rn(xr * sn + xi * c);
    }
    __syncthreads();
    const __half* kvs = kv + (size_t)s * (NH * (DN + DV));
    for (int idx = threadIdx.x; idx < NH * QKD; idx += 256) {
        int h = idx / QKD, d = idx - h * QKD;
        if (d < DN) {
            Kb[((size_t)h * S + s) * QKD + d] = kvs[h * (DN + DV) + d];
        } else {
            Kb[((size_t)h * S + s) * QKD + d] = rot[d - DN];
        }
    }
}

// ---------------- V transpose: kv half [s][h][DN+d] -> Vt half [h][d][s] ----------------
__global__ void vtrans(const __half* __restrict__ kv, __half* __restrict__ Vt) {
    const int h = blockIdx.x, d0 = blockIdx.y * 32, s0 = blockIdx.z * 64;
    __shared__ __half tile[32][65];
    const int dl = threadIdx.x & 31, sl = threadIdx.x >> 5;
    for (int ss = sl; ss < 64; ss += 8)
        tile[dl][ss] = kv[(size_t)(s0 + ss) * (NH * (DN + DV)) + h * (DN + DV) + DN + d0 + dl];
    __syncthreads();
    const int sl2 = threadIdx.x & 63, dl2 = threadIdx.x >> 6;
    for (int dd = dl2; dd < 32; dd += 4)
        Vt[((size_t)h * DV + d0 + dd) * S + s0 + sl2] = tile[dd][sl2];
}

// ---------------- host ----------------
static void* sym_addr(const void* symbol) {
    void* p = nullptr;
    cudaGetSymbolAddress(&p, symbol);
    return p;
}

static void launch_half(const float* src, __half* dst, size_t n) {
    int n4 = (int)(n / 4);
    to_half_kernel<<<(n4 + 255) / 256, 256>>>((const float4*)src, (uint2*)dst, n4);
}

static void launch_gemm_f(const __half* A, const __half* B, float* C, int M, int N, int K) {
    dim3 grid((N + HBN - 1) / HBN, M / HBM);
    gemm_h<false><<<grid, 256, GEMM_SMEM>>>(A, B, C, M, N, K);
}
static void launch_gemm_hh(const __half* A, const __half* B, __half* C, int M, int N, int K) {
    dim3 grid((N + HBN - 1) / HBN, M / HBM);
    gemm_h<true><<<grid, 256, GEMM_SMEM>>>(A, B, C, M, N, K);
}

extern "C" void kernel_launch(void* const* d_in, const int* in_sizes, int n_in,
                              void* d_out, int out_size) {
    const float* hidden    = (const float*)d_in[0];
    const float* freqs     = (const float*)d_in[1];
    const float* q_a_w     = (const float*)d_in[2];
    const float* q_a_ln_w  = (const float*)d_in[3];
    const float* q_b_w     = (const float*)d_in[4];
    const float* kv_a_w    = (const float*)d_in[5];
    const float* kv_a_ln_w = (const float*)d_in[6];
    const float* kv_b_w    = (const float*)d_in[7];
    const float* o_w       = (const float*)d_in[8];
    float* out = (float*)d_out;

    float*  qackv = (float*) sym_addr(g_qackv);
    __half* qan   = (__half*)sym_addr(g_qan);
    __half* q     = (__half*)sym_addr(g_q);
    __half* ckvn  = (__half*)sym_addr(g_ckvn);
    __half* kv    = (__half*)sym_addr(g_kv);
    __half* Qb    = (__half*)sym_addr(g_Q);
    __half* Kb    = (__half*)sym_addr(g_K);
    __half* Vt    = (__half*)sym_addr(g_Vt);
    __half* attn  = (__half*)sym_addr(g_attn);
    __half* hid   = (__half*)sym_addr(g_hid);
    __half* w1    = (__half*)sym_addr(g_w1);
    __half* qbw   = (__half*)sym_addr(g_qbw);
    __half* kvbw  = (__half*)sym_addr(g_kvbw);
    __half* ow    = (__half*)sym_addr(g_ow);

    cudaFuncSetAttribute(flash_attn, cudaFuncAttributeMaxDynamicSharedMemorySize, FLASH_SMEM);
    cudaFuncSetAttribute(gemm_h<false>, cudaFuncAttributeMaxDynamicSharedMemorySize, GEMM_SMEM);
    cudaFuncSetAttribute(gemm_h<true>,  cudaFuncAttributeMaxDynamicSharedMemorySize, GEMM_SMEM);

    // 0) convert inputs to fp16 once per call
    launch_half(hidden, hid,  (size_t)S * Hh);
    launch_half(q_a_w,  w1,                    (size_t)RQ * Hh);
    launch_half(kv_a_w, w1 + (size_t)RQ * Hh,  (size_t)CKVW * Hh);
    launch_half(q_b_w,  qbw,  (size_t)NH * QKD * RQ);
    launch_half(kv_b_w, kvbw, (size_t)NH * (DN + DV) * RKV);
    launch_half(o_w,    ow,   (size_t)Hh * Hh);

    // 1) [q_a | ckv] = hid @ w1^T   [2048, 2112] (f32 out for rmsnorm + k_rot)
    launch_gemm_f(hid, w1, qackv, S, W1N, Hh);
    // 2) rmsnorm(q_a) -> half
    rmsnorm_kernel<<<S, 256>>>(qackv, q_a_ln_w, qan, RQ, W1N, RQ);
    // 3) q = qan @ qbw^T            [2048,6144] (half out)
    launch_gemm_hh(qan, qbw, q, S, NH * QKD, RQ);
    // 5) rmsnorm(ckv[:, :512]) -> half
    rmsnorm_kernel<<<S, 256>>>(qackv + RQ, kv_a_ln_w, ckvn, RKV, W1N, RKV);
    // 6) kv = ckvn @ kvbw^T         [2048,8192] (half out)
    launch_gemm_hh(ckvn, kvbw, kv, S, NH * (DN + DV), RKV);
    // 7) assemble Q with RoPE (half)
    build_q2<<<S, 256>>>(q, freqs, Qb);
    // 8) assemble K (half); V transposed [h][d][s]
    build_k2<<<S, 256>>>(kv, qackv, freqs, Kb);
    vtrans<<<dim3(NH, DV / 32, S / 64), 256>>>(kv, Vt);
    // 9-11) fused flash attention -> attn (half)
    flash_attn<<<dim3(S / 128, NH), 256, FLASH_SMEM>>>(Qb, Kb, Vt, attn);
    // 12) out = attn @ ow^T         [2048,4096] (f32 out)
    launch_gemm_f(attn, ow, out, S, Hh, Hh);
}